// round 16
// baseline (speedup 1.0000x reference)
#include <cuda_runtime.h>
#include <cuda_bf16.h>
#include <cstdint>

// ---------------- static config ----------------
namespace cfg {
constexpr int NN = 10000;
constexpr int NE = 128000;
constexpr int NWARP = 9;
constexpr int THREADS = NWARP * 32;     // 288
constexpr int NBLK = NE / 32;           // 4000 32-edge blocks (2 M-tiles each)

// smem byte offsets
constexpr int OFF_B2F   = 0;            // fc2 weight frags: [52 nt][4 ks][32 lane] uint4 = 106496B
constexpr int OFF_B1F   = 106496;       // fc1 weight frags: [8 nt][3 ks][32 lane] uint4 = 12288B
constexpr int OFF_BIAS2 = 118784;       // 416 f32
constexpr int OFF_BIAS1 = 120448;       // 64 f32
constexpr int OFF_SLAB  = 120704;       // per-warp slabs: 1664 f32 each
constexpr int SLABF     = 1664;
constexpr int SMEM_BYTES = OFF_SLAB + NWARP * SLABF * 4;   // 180608
}

// ---------------- helpers ----------------
__device__ __forceinline__ void split2(float x, float y, uint32_t& h, uint32_t& l) {
    __nv_bfloat162 hb = __floats2bfloat162_rn(x, y);        // x -> low, y -> high
    h = *(const uint32_t*)&hb;
    float rx = x - __bfloat162float(hb.x);
    float ry = y - __bfloat162float(hb.y);
    __nv_bfloat162 lb = __floats2bfloat162_rn(rx, ry);
    l = *(const uint32_t*)&lb;
}
__device__ __forceinline__ void mma16816(float (&d)[4], const uint32_t (&a)[4],
                                         uint32_t b0, uint32_t b1) {
    asm volatile(
        "mma.sync.aligned.m16n8k16.row.col.f32.bf16.bf16.f32 "
        "{%0,%1,%2,%3}, {%4,%5,%6,%7}, {%8,%9}, {%0,%1,%2,%3};"
        : "+f"(d[0]), "+f"(d[1]), "+f"(d[2]), "+f"(d[3])
        : "r"(a[0]), "r"(a[1]), "r"(a[2]), "r"(a[3]), "r"(b0), "r"(b1));
}

// ---------------- device scratch ----------------
__device__ float g_h0[cfg::NN * 16];
__device__ float g_h1[cfg::NN * 12];
__device__ float g_acc0[cfg::NN * 16];
__device__ float g_acc1[cfg::NN * 12];
__device__ float g_cnt[cfg::NN];
__device__ float g_eattr[cfg::NE * 16];
__device__ float g_y1[cfg::NE * 3];
// pre-packed weight fragments, both layers
__device__ uint4 g_B2F[2 * 52 * 4 * 32];   // 212992 B
__device__ uint4 g_B1F[2 * 8 * 3 * 32];    // 24576 B

// ---------------- zero scratch + pack weight fragments (both layers) ----------------
__global__ void zero_pack_kernel(const float* __restrict__ fc1W,
                                 const float* __restrict__ fc2W) {
    int i = blockIdx.x * blockDim.x + threadIdx.x;
    int stride = gridDim.x * blockDim.x;

    // pack region: first 2*6656 items -> B2F, next 2*768 -> B1F
    if (i < 2 * 6656) {
        int layer = i / 6656, t = i - layer * 6656;
        const float* W2g = fc2W + layer * 64 * 416;
        int nt = t >> 7, rem = t & 127, ks = rem >> 5, ln = rem & 31;
        int gg = ln >> 2, cc = ln & 3;
        int n = nt * 8 + gg, k0 = ks * 16 + 2 * cc;
        uint32_t hx, lx, hy, ly;
        split2(W2g[k0 * 416 + n], W2g[(k0 + 1) * 416 + n], hx, lx);
        split2(W2g[(k0 + 8) * 416 + n], W2g[(k0 + 9) * 416 + n], hy, ly);
        g_B2F[layer * 6656 + t] = make_uint4(hx, hy, lx, ly);
    } else if (i < 2 * 6656 + 2 * 768) {
        int j = i - 2 * 6656;
        int layer = j / 768, t = j - layer * 768;
        const float* W1g = fc1W + layer * 48 * 64;
        int nt = t / 96, rem = t % 96, ks = rem >> 5, ln = rem & 31;
        int gg = ln >> 2, cc = ln & 3;
        int n = nt * 8 + gg, k0 = ks * 16 + 2 * cc;
        uint32_t hx, lx, hy, ly;
        split2(W1g[k0 * 64 + n], W1g[(k0 + 1) * 64 + n], hx, lx);
        split2(W1g[(k0 + 8) * 64 + n], W1g[(k0 + 9) * 64 + n], hy, ly);
        g_B1F[layer * 768 + t] = make_uint4(hx, hy, lx, ly);
    }

    // zero region (grid-stride, all threads)
    for (int t = i; t < cfg::NN * 16; t += stride) g_acc0[t] = 0.f;
    for (int t = i; t < cfg::NN * 12; t += stride) { g_acc1[t] = 0.f; g_h1[t] = 0.f; }
    for (int t = i; t < cfg::NN; t += stride) g_cnt[t] = 0.f;
}

// ---------------- node encoder + node_embedding MLP ----------------
__global__ void node_init_kernel(const float* __restrict__ nf,
                                 const float* __restrict__ encW, const float* __restrict__ encB,
                                 const float* __restrict__ W1, const float* __restrict__ B1,
                                 const float* __restrict__ W2, const float* __restrict__ B2) {
    int n = blockIdx.x * blockDim.x + threadIdx.x;
    if (n >= cfg::NN) return;
    float enc[16];
    #pragma unroll
    for (int c = 0; c < 16; c++) enc[c] = encB[c];
    for (int f = 0; f < 64; f++) {
        float v = nf[n * 64 + f];
        #pragma unroll
        for (int c = 0; c < 16; c++) enc[c] = fmaf(v, encW[f * 16 + c], enc[c]);
    }
    float t[16];
    #pragma unroll
    for (int c = 0; c < 16; c++) {
        float a = B1[c];
        #pragma unroll
        for (int j = 0; j < 16; j++) a = fmaf(enc[j], W1[j * 16 + c], a);
        t[c] = fmaxf(a, 0.f);
    }
    #pragma unroll
    for (int c = 0; c < 16; c++) {
        float a = B2[c];
        #pragma unroll
        for (int j = 0; j < 16; j++) a = fmaf(t[j], W2[j * 16 + c], a);
        g_h0[n * 16 + c] = a;
    }
}

// ---------------- per-edge init (fast RBF via anchored recurrence) ----------------
__global__ void edge_init_kernel(const float* __restrict__ pos,
                                 const float* __restrict__ eain, const int* __restrict__ ei,
                                 const float* __restrict__ eeW1, const float* __restrict__ eeB1,
                                 const float* __restrict__ eeW2, const float* __restrict__ eeB2,
                                 const float* __restrict__ reW1, const float* __restrict__ reB1,
                                 const float* __restrict__ reW2, const float* __restrict__ reB2) {
    int e = blockIdx.x * blockDim.x + threadIdx.x;
    if (e >= cfg::NE) return;
    int sn = ei[e], dn = ei[cfg::NE + e];
    float vx = pos[sn * 3 + 0] - pos[dn * 3 + 0];
    float vy = pos[sn * 3 + 1] - pos[dn * 3 + 1];
    float vz = pos[sn * 3 + 2] - pos[dn * 3 + 2];
    float d = sqrtf(vx * vx + vy * vy + vz * vz);
    float dmx = fmaxf(d, 1e-9f);
    float s = 1.7320508075688772f / dmx;
    g_y1[e * 3 + 0] = s * vx;
    g_y1[e * 3 + 1] = s * vy;
    g_y1[e * 3 + 2] = s * vz;
    atomicAdd(&g_cnt[sn], 1.f);

    float xin[16];
    #pragma unroll
    for (int j = 0; j < 16; j++) xin[j] = eain[e * 16 + j];
    float he[16];
    #pragma unroll
    for (int c = 0; c < 16; c++) {
        float a = eeB1[c];
        #pragma unroll
        for (int j = 0; j < 16; j++) a = fmaf(xin[j], eeW1[j * 16 + c], a);
        he[c] = fmaxf(a, 0.f);
    }
    // fast RBF: Gaussian over uniform grid via anchored multiplicative recurrence.
    // G_r = exp(coeff*(d - r*step)^2);  upward: G_{r+1} = G_r*Rup, Rup *= K2.
    const float step = 12.0f / 31.0f;
    const float coeff = -0.5f / (step * step);
    const float K2 = __expf(2.0f * coeff * step * step);
    float hr[16];
    #pragma unroll
    for (int c = 0; c < 16; c++) hr[c] = reB1[c];
    {
        int r0 = (int)rintf(d / step);
        r0 = (r0 < 0) ? 0 : ((r0 > 31) ? 31 : r0);
        float delta = d - (float)r0 * step;
        float A = __expf(coeff * delta * delta);           // G_{r0} (peak, <= ~1)
        float Rup = __expf(coeff * step * (step - 2.0f * delta));
        float Rdn = __expf(coeff * step * (step + 2.0f * delta));
        float G = A;
        for (int r = r0; r < 32; r++) {                    // upward incl. r0
            #pragma unroll
            for (int c = 0; c < 16; c++) hr[c] = fmaf(G, reW1[r * 16 + c], hr[c]);
            G *= Rup; Rup *= K2;
        }
        G = A * Rdn;
        for (int r = r0 - 1; r >= 0; r--) {                // downward
            #pragma unroll
            for (int c = 0; c < 16; c++) hr[c] = fmaf(G, reW1[r * 16 + c], hr[c]);
            Rdn *= K2; G *= Rdn;
        }
    }
    #pragma unroll
    for (int c = 0; c < 16; c++) hr[c] = fmaxf(hr[c], 0.f);
    #pragma unroll
    for (int c = 0; c < 16; c++) {
        float a = eeB2[c] + reB2[c];
        #pragma unroll
        for (int j = 0; j < 16; j++)
            a = fmaf(he[j], eeW2[j * 16 + c], fmaf(hr[j], reW2[j * 16 + c], a));
        g_eattr[e * 16 + c] = a;
    }
}

// ---------------- conv layer: mma.sync split-bf16, 2 M-tiles per warp ----------------
__global__ void __launch_bounds__(cfg::THREADS, 1)
conv_kernel(const int* __restrict__ ei, int layer,
            const float* __restrict__ B1g, const float* __restrict__ B2g) {
    extern __shared__ char sm[];
    uint4* B2F = (uint4*)(sm + cfg::OFF_B2F);
    uint4* B1F = (uint4*)(sm + cfg::OFF_B1F);
    float* bias2s = (float*)(sm + cfg::OFF_BIAS2);
    float* bias1s = (float*)(sm + cfg::OFF_BIAS1);
    const int tid = threadIdx.x, lane = tid & 31, warp = tid >> 5;
    const int g = lane >> 2, c = lane & 3;

    // ---- coalesced copy of pre-packed weight fragments ----
    const uint4* src2 = g_B2F + layer * 6656;
    const uint4* src1 = g_B1F + layer * 768;
    for (int t = tid; t < 6656; t += cfg::THREADS) B2F[t] = src2[t];
    for (int t = tid; t < 768; t += cfg::THREADS) B1F[t] = src1[t];
    for (int t = tid; t < 416; t += cfg::THREADS) bias2s[t] = B2g[t];
    for (int t = tid; t < 64; t += cfg::THREADS) bias1s[t] = B1g[t];
    __syncthreads();

    float* sl  = (float*)(sm + cfg::OFF_SLAB) + warp * cfg::SLABF;
    float* X0  = sl;           // [32][20]
    float* X1  = sl + 640;     // [32][12]
    float* DOT = sl + 1024;    // [32][4]
    float* CR  = sl + 1152;    // [32][12]
    float* Y1s = sl + 1536;    // [32][3]

    const unsigned FULL = 0xffffffffu;
    const float n0sc = 0.22360679774997896f;   // 1/sqrt(20)
    const float n1sc = 0.20412414523193150f;   // 1/sqrt(24)

    for (int blk = blockIdx.x * cfg::NWARP + warp; blk < cfg::NBLK;
         blk += gridDim.x * cfg::NWARP) {
        const int ebase = blk * 32;

        // ---- stage per-edge data: each lane owns one of 32 edges ----
        {
            int e = lane, ge = ebase + e;
            int dn = ei[cfg::NE + ge];
            const float4* p = (const float4*)(g_h0 + (size_t)dn * 16);
            *(float4*)(X0 + e * 20 + 0)  = p[0];
            *(float4*)(X0 + e * 20 + 4)  = p[1];
            *(float4*)(X0 + e * 20 + 8)  = p[2];
            *(float4*)(X0 + e * 20 + 12) = p[3];
            float ya = g_y1[ge * 3 + 0], yb = g_y1[ge * 3 + 1], yc = g_y1[ge * 3 + 2];
            Y1s[e * 3 + 0] = ya; Y1s[e * 3 + 1] = yb; Y1s[e * 3 + 2] = yc;
            float x1r[12];
            #pragma unroll
            for (int q = 0; q < 3; q++)
                ((float4*)x1r)[q] = ((const float4*)(g_h1 + (size_t)dn * 12))[q];
            #pragma unroll
            for (int n = 0; n < 4; n++) {
                float xa = x1r[n*3], xb = x1r[n*3+1], xc = x1r[n*3+2];
                X1[e*12 + n*3 + 0] = xa; X1[e*12 + n*3 + 1] = xb; X1[e*12 + n*3 + 2] = xc;
                DOT[e*4 + n] = (xa*ya + xb*yb + xc*yc) * 0.57735026918962576f;
                CR[e*12 + n*3 + 0] = (xb*yc - xc*yb) * 0.70710678118654752f;
                CR[e*12 + n*3 + 1] = (xc*ya - xa*yc) * 0.70710678118654752f;
                CR[e*12 + n*3 + 2] = (xa*yb - xb*ya) * 0.70710678118654752f;
            }
        }
        __syncwarp();

        // ---- fc1 per tile -> fc2 A-fragments (register chain) ----
        uint32_t a2h[2][4][4], a2l[2][4][4];
        #pragma unroll
        for (int t = 0; t < 2; t++) {
            const int gx0 = ebase + t * 16 + g, gx1 = gx0 + 8;
            const int sn0 = ei[gx0], sn1 = ei[gx1];
            const int dn0 = ei[cfg::NE + gx0], dn1 = ei[cfg::NE + gx1];
            const float* seg0[3] = { g_eattr + (size_t)gx0 * 16, g_h0 + (size_t)sn0 * 16, g_h0 + (size_t)dn0 * 16 };
            const float* seg1[3] = { g_eattr + (size_t)gx1 * 16, g_h0 + (size_t)sn1 * 16, g_h0 + (size_t)dn1 * 16 };

            uint32_t a1h[3][4], a1l[3][4];
            #pragma unroll
            for (int ks = 0; ks < 3; ks++) {
                float2 r0lo = *(const float2*)(seg0[ks] + 2 * c);
                float2 r0hi = *(const float2*)(seg0[ks] + 2 * c + 8);
                float2 r1lo = *(const float2*)(seg1[ks] + 2 * c);
                float2 r1hi = *(const float2*)(seg1[ks] + 2 * c + 8);
                split2(r0lo.x, r0lo.y, a1h[ks][0], a1l[ks][0]);
                split2(r1lo.x, r1lo.y, a1h[ks][1], a1l[ks][1]);
                split2(r0hi.x, r0hi.y, a1h[ks][2], a1l[ks][2]);
                split2(r1hi.x, r1hi.y, a1h[ks][3], a1l[ks][3]);
            }
            float d1[8][4];
            #pragma unroll
            for (int nt = 0; nt < 8; nt++) { d1[nt][0]=0.f; d1[nt][1]=0.f; d1[nt][2]=0.f; d1[nt][3]=0.f; }
            #pragma unroll
            for (int nt = 0; nt < 8; nt++)
                #pragma unroll
                for (int ks = 0; ks < 3; ks++) {
                    uint4 B = B1F[(nt * 3 + ks) * 32 + lane];
                    mma16816(d1[nt], a1h[ks], B.x, B.y);
                    mma16816(d1[nt], a1h[ks], B.z, B.w);
                    mma16816(d1[nt], a1l[ks], B.x, B.y);
                }
            #pragma unroll
            for (int nt = 0; nt < 8; nt++) {
                float b0 = bias1s[nt * 8 + 2 * c], b1 = bias1s[nt * 8 + 2 * c + 1];
                float v0 = fmaxf(d1[nt][0] + b0, 0.f), v1 = fmaxf(d1[nt][1] + b1, 0.f);
                float v2 = fmaxf(d1[nt][2] + b0, 0.f), v3 = fmaxf(d1[nt][3] + b1, 0.f);
                int ks2 = nt >> 1, sl2 = (nt & 1) * 2;
                split2(v0, v1, a2h[t][ks2][sl2],     a2l[t][ks2][sl2]);
                split2(v2, v3, a2h[t][ks2][sl2 + 1], a2l[t][ks2][sl2 + 1]);
            }
        }

        // ---- fc2 + tensor-product contraction, per column-pair, both tiles ----
        float o0a[2][2][4];
        #pragma unroll
        for (int t = 0; t < 2; t++)
            #pragma unroll
            for (int r = 0; r < 2; r++) { o0a[t][r][0]=0.f; o0a[t][r][1]=0.f; o0a[t][r][2]=0.f; o0a[t][r][3]=0.f; }
        float t011p[2][2][2] = {{{0.f,0.f},{0.f,0.f}},{{0.f,0.f},{0.f,0.f}}};
        float o1p[2][2][2][3];
        #pragma unroll
        for (int t = 0; t < 2; t++)
            #pragma unroll
            for (int r = 0; r < 2; r++)
                #pragma unroll
                for (int s = 0; s < 2; s++) { o1p[t][r][s][0]=0.f; o1p[t][r][s][1]=0.f; o1p[t][r][s][2]=0.f; }

        #define FC2_PAIR(j, dA, dB)                                             \
            float dA[2][4] = {{0.f,0.f,0.f,0.f},{0.f,0.f,0.f,0.f}};             \
            float dB[2][4] = {{0.f,0.f,0.f,0.f},{0.f,0.f,0.f,0.f}};             \
            {   int ntA = 2 * (j);                                              \
                _Pragma("unroll")                                               \
                for (int ks = 0; ks < 4; ks++) {                                \
                    uint4 BA = B2F[(ntA * 4 + ks) * 32 + lane];                 \
                    uint4 BB = B2F[((ntA + 1) * 4 + ks) * 32 + lane];           \
                    _Pragma("unroll")                                           \
                    for (int t = 0; t < 2; t++) {                               \
                        mma16816(dA[t], a2h[t][ks], BA.x, BA.y);                \
                        mma16816(dA[t], a2h[t][ks], BA.z, BA.w);                \
                        mma16816(dA[t], a2l[t][ks], BA.x, BA.y);                \
                        mma16816(dB[t], a2h[t][ks], BB.x, BB.y);                \
                        mma16816(dB[t], a2h[t][ks], BB.z, BB.w);                \
                        mma16816(dB[t], a2l[t][ks], BB.x, BB.y);                \
                    }                                                           \
                } }                                                             \
            {   float bA0 = bias2s[16*(j) + 2*c],     bA1 = bias2s[16*(j) + 2*c + 1]; \
                float bB0 = bias2s[16*(j) + 8 + 2*c], bB1 = bias2s[16*(j) + 9 + 2*c]; \
                _Pragma("unroll")                                               \
                for (int t = 0; t < 2; t++) {                                   \
                    dA[t][0] += bA0; dA[t][1] += bA1; dA[t][2] += bA0; dA[t][3] += bA1; \
                    dB[t][0] += bB0; dB[t][1] += bB1; dB[t][2] += bB0; dB[t][3] += bB1; \
                } }

        // pairs 0..15: w00  (o0 += x0[n=j] * w)
        for (int j = 0; j < 16; j++) {
            FC2_PAIR(j, dA, dB);
            #pragma unroll
            for (int t = 0; t < 2; t++) {
                int e0 = t * 16 + g, e1 = e0 + 8;
                float xa = X0[e0 * 20 + j], xb = X0[e1 * 20 + j];
                o0a[t][0][0] = fmaf(xa, dA[t][0], o0a[t][0][0]); o0a[t][0][1] = fmaf(xa, dA[t][1], o0a[t][0][1]);
                o0a[t][0][2] = fmaf(xa, dB[t][0], o0a[t][0][2]); o0a[t][0][3] = fmaf(xa, dB[t][1], o0a[t][0][3]);
                o0a[t][1][0] = fmaf(xb, dA[t][2], o0a[t][1][0]); o0a[t][1][1] = fmaf(xb, dA[t][3], o0a[t][1][1]);
                o0a[t][1][2] = fmaf(xb, dB[t][2], o0a[t][1][2]); o0a[t][1][3] = fmaf(xb, dB[t][3], o0a[t][1][3]);
            }
        }
        // pairs 16..19: w011 (t011[o] += x0[n] * w)
        for (int j = 16; j < 20; j++) {
            FC2_PAIR(j, dA, dB);
            int nA = 4 * (j - 16) + (c >> 1), nB = nA + 2;
            #pragma unroll
            for (int t = 0; t < 2; t++) {
                int e0 = t * 16 + g, e1 = e0 + 8;
                float xa0 = X0[e0*20 + nA], xb0 = X0[e0*20 + nB];
                float xa1 = X0[e1*20 + nA], xb1 = X0[e1*20 + nB];
                t011p[t][0][0] += xa0 * dA[t][0] + xb0 * dB[t][0];
                t011p[t][0][1] += xa0 * dA[t][1] + xb0 * dB[t][1];
                t011p[t][1][0] += xa1 * dA[t][2] + xb1 * dB[t][2];
                t011p[t][1][1] += xa1 * dA[t][3] + xb1 * dB[t][3];
            }
        }
        // pair 20: w101 (o1[o][m] += x1[n][m] * w)
        {
            FC2_PAIR(20, dA, dB);
            int nA = c >> 1, nB = nA + 2;
            #pragma unroll
            for (int t = 0; t < 2; t++) {
                int e0 = t * 16 + g, e1 = e0 + 8;
                #pragma unroll
                for (int m = 0; m < 3; m++) {
                    float xa0 = X1[e0*12 + nA*3 + m], xb0 = X1[e0*12 + nB*3 + m];
                    float xa1 = X1[e1*12 + nA*3 + m], xb1 = X1[e1*12 + nB*3 + m];
                    o1p[t][0][0][m] += xa0 * dA[t][0] + xb0 * dB[t][0];
                    o1p[t][0][1][m] += xa0 * dA[t][1] + xb0 * dB[t][1];
                    o1p[t][1][0][m] += xa1 * dA[t][2] + xb1 * dB[t][2];
                    o1p[t][1][1][m] += xa1 * dA[t][3] + xb1 * dB[t][3];
                }
            }
        }
        // pairs 21..24: w110 (o0 += dot[n=j-21] * w)
        for (int j = 21; j < 25; j++) {
            FC2_PAIR(j, dA, dB);
            #pragma unroll
            for (int t = 0; t < 2; t++) {
                int e0 = t * 16 + g, e1 = e0 + 8;
                float da = DOT[e0*4 + (j - 21)], db = DOT[e1*4 + (j - 21)];
                o0a[t][0][0] = fmaf(da, dA[t][0], o0a[t][0][0]); o0a[t][0][1] = fmaf(da, dA[t][1], o0a[t][0][1]);
                o0a[t][0][2] = fmaf(da, dB[t][0], o0a[t][0][2]); o0a[t][0][3] = fmaf(da, dB[t][1], o0a[t][0][3]);
                o0a[t][1][0] = fmaf(db, dA[t][2], o0a[t][1][0]); o0a[t][1][1] = fmaf(db, dA[t][3], o0a[t][1][1]);
                o0a[t][1][2] = fmaf(db, dB[t][2], o0a[t][1][2]); o0a[t][1][3] = fmaf(db, dB[t][3], o0a[t][1][3]);
            }
        }
        // pair 25: w111 (o1 += cr[n][m] * w)
        {
            FC2_PAIR(25, dA, dB);
            int nA = c >> 1, nB = nA + 2;
            #pragma unroll
            for (int t = 0; t < 2; t++) {
                int e0 = t * 16 + g, e1 = e0 + 8;
                #pragma unroll
                for (int m = 0; m < 3; m++) {
                    float xa0 = CR[e0*12 + nA*3 + m], xb0 = CR[e0*12 + nB*3 + m];
                    float xa1 = CR[e1*12 + nA*3 + m], xb1 = CR[e1*12 + nB*3 + m];
                    o1p[t][0][0][m] += xa0 * dA[t][0] + xb0 * dB[t][0];
                    o1p[t][0][1][m] += xa0 * dA[t][1] + xb0 * dB[t][1];
                    o1p[t][1][0][m] += xa1 * dA[t][2] + xb1 * dB[t][2];
                    o1p[t][1][1][m] += xa1 * dA[t][3] + xb1 * dB[t][3];
                }
            }
        }
        #undef FC2_PAIR

        // ---- l=0 scatter ----
        #pragma unroll
        for (int t = 0; t < 2; t++)
            #pragma unroll
            for (int r = 0; r < 2; r++) {
                int sn = ei[ebase + t * 16 + g + r * 8];
                #pragma unroll
                for (int s = 0; s < 4; s++) {
                    int o = (s < 2) ? (2 * c + s) : (8 + 2 * c + (s - 2));
                    atomicAdd(&g_acc0[sn * 16 + o], n0sc * o0a[t][r][s]);
                }
            }
        // ---- l=1: reduce across c<->c^2, add t011*y1, scatter ----
        #pragma unroll
        for (int t = 0; t < 2; t++)
            #pragma unroll
            for (int r = 0; r < 2; r++)
                #pragma unroll
                for (int s = 0; s < 2; s++) {
                    t011p[t][r][s] += __shfl_xor_sync(FULL, t011p[t][r][s], 2);
                    #pragma unroll
                    for (int m = 0; m < 3; m++)
                        o1p[t][r][s][m] += __shfl_xor_sync(FULL, o1p[t][r][s][m], 2);
                }
        if (c < 2) {
            #pragma unroll
            for (int t = 0; t < 2; t++)
                #pragma unroll
                for (int r = 0; r < 2; r++) {
                    int e = t * 16 + g + r * 8;
                    int sn = ei[ebase + e];
                    #pragma unroll
                    for (int s = 0; s < 2; s++) {
                        int o = 2 * c + s;
                        float tt = t011p[t][r][s];
                        #pragma unroll
                        for (int m = 0; m < 3; m++) {
                            float val = o1p[t][r][s][m] + tt * Y1s[e * 3 + m];
                            atomicAdd(&g_acc1[sn * 12 + o * 3 + m], n1sc * val);
                        }
                    }
                }
        }
        __syncwarp();
    }
}

// ---------------- scatter-mean residual update ----------------
__global__ void update_kernel() {
    int i = blockIdx.x * blockDim.x + threadIdx.x;
    if (i < cfg::NN * 16) {
        int n = i >> 4;
        float inv = 1.f / fmaxf(g_cnt[n], 1.f);
        g_h0[i] += g_acc0[i] * inv;
        g_acc0[i] = 0.f;
    }
    if (i < cfg::NN * 12) {
        int n = i / 12;
        float inv = 1.f / fmaxf(g_cnt[n], 1.f);
        g_h1[i] += g_acc1[i] * inv;
        g_acc1[i] = 0.f;
    }
}

// ---------------- final update + o3.Linear + sorter ----------------
__global__ void final_kernel(float* __restrict__ out,
                             const float* __restrict__ lin0, const float* __restrict__ lin1) {
    int n = blockIdx.x * blockDim.x + threadIdx.x;
    if (n >= cfg::NN) return;
    float inv = 1.f / fmaxf(g_cnt[n], 1.f);
    float h0f[16];
    #pragma unroll
    for (int s = 0; s < 16; s++) h0f[s] = g_h0[n * 16 + s] + g_acc0[n * 16 + s] * inv;
    float h1f[12];
    #pragma unroll
    for (int s = 0; s < 12; s++) h1f[s] = g_h1[n * 12 + s] + g_acc1[n * 12 + s] * inv;
    float* o = out + (size_t)n * 128;
    #pragma unroll 4
    for (int cc = 0; cc < 32; cc++) {
        float f0 = 0.f;
        #pragma unroll
        for (int s = 0; s < 16; s++) f0 = fmaf(h0f[s], lin0[s * 32 + cc], f0);
        o[4 * cc] = 0.25f * f0;
        #pragma unroll
        for (int m = 0; m < 3; m++) {
            float f1 = 0.f;
            #pragma unroll
            for (int v = 0; v < 4; v++) f1 = fmaf(h1f[v * 3 + m], lin1[v * 32 + cc], f1);
            o[4 * cc + 1 + m] = 0.5f * f1;
        }
    }
}

// ---------------- launch ----------------
extern "C" void kernel_launch(void* const* d_in, const int* in_sizes, int n_in,
                              void* d_out, int out_size) {
    const float* pos          = (const float*)d_in[0];
    const float* node_feats   = (const float*)d_in[1];
    const float* edge_attr_in = (const float*)d_in[2];
    const int*   edge_index   = (const int*)d_in[3];
    const float* enc_W  = (const float*)d_in[4];
    const float* enc_b  = (const float*)d_in[5];
    const float* ne_W1  = (const float*)d_in[6];
    const float* ne_b1  = (const float*)d_in[7];
    const float* ne_W2  = (const float*)d_in[8];
    const float* ne_b2  = (const float*)d_in[9];
    const float* ee_W1  = (const float*)d_in[10];
    const float* ee_b1  = (const float*)d_in[11];
    const float* ee_W2  = (const float*)d_in[12];
    const float* ee_b2  = (const float*)d_in[13];
    const float* re_W1  = (const float*)d_in[14];
    const float* re_b1  = (const float*)d_in[15];
    const float* re_W2  = (const float*)d_in[16];
    const float* re_b2  = (const float*)d_in[17];
    const float* fc1_W  = (const float*)d_in[18];   // [2,48,64]
    const float* fc1_b  = (const float*)d_in[19];   // [2,64]
    const float* fc2_W  = (const float*)d_in[20];   // [2,64,416]
    const float* fc2_b  = (const float*)d_in[21];   // [2,416]
    const float* lin0_W = (const float*)d_in[22];
    const float* lin1_W = (const float*)d_in[23];
    float* out = (float*)d_out;

    int dev = 0;
    cudaGetDevice(&dev);
    int nsm = 148;
    cudaDeviceGetAttribute(&nsm, cudaDevAttrMultiProcessorCount, dev);
    cudaFuncSetAttribute(conv_kernel, cudaFuncAttributeMaxDynamicSharedMemorySize, cfg::SMEM_BYTES);

    zero_pack_kernel<<<256, 256>>>(fc1_W, fc2_W);
    node_init_kernel<<<(cfg::NN + 127) / 128, 128>>>(node_feats, enc_W, enc_b,
                                                     ne_W1, ne_b1, ne_W2, ne_b2);
    edge_init_kernel<<<(cfg::NE + 127) / 128, 128>>>(pos, edge_attr_in, edge_index,
                                                     ee_W1, ee_b1, ee_W2, ee_b2,
                                                     re_W1, re_b1, re_W2, re_b2);
    // layer 0
    conv_kernel<<<nsm, cfg::THREADS, cfg::SMEM_BYTES>>>(edge_index, 0, fc1_b, fc2_b);
    update_kernel<<<(cfg::NN * 16 + 255) / 256, 256>>>();
    // layer 1
    conv_kernel<<<nsm, cfg::THREADS, cfg::SMEM_BYTES>>>(edge_index, 1,
        fc1_b + 64, fc2_b + 416);
    // final
    final_kernel<<<(cfg::NN + 127) / 128, 128>>>(out, lin0_W, lin1_W);
}

// round 17
// speedup vs baseline: 1.4243x; 1.4243x over previous
#include <cuda_runtime.h>
#include <cuda_bf16.h>
#include <cstdint>

// ---------------- static config ----------------
namespace cfg {
constexpr int NN = 10000;
constexpr int NE = 128000;
constexpr int NWARP = 9;
constexpr int THREADS = NWARP * 32;     // 288
constexpr int NBLK = NE / 32;           // 4000 32-edge blocks (2 M-tiles each)

// fused node+edge init partition (256 threads/block)
constexpr int NE_ND_BLKS = (NN + 255) / 256;    // 40
constexpr int NE_EG_BLKS = (NE + 255) / 256;    // 500
constexpr int NE_BLKS = NE_ND_BLKS + NE_EG_BLKS;

// smem byte offsets
constexpr int OFF_B2F   = 0;            // fc2 weight frags: [52 nt][4 ks][32 lane] uint4 = 106496B
constexpr int OFF_B1F   = 106496;       // fc1 weight frags: [8 nt][3 ks][32 lane] uint4 = 12288B
constexpr int OFF_BIAS2 = 118784;       // 416 f32
constexpr int OFF_BIAS1 = 120448;       // 64 f32
constexpr int OFF_SLAB  = 120704;       // per-warp slabs: 1664 f32 each
constexpr int SLABF     = 1664;
constexpr int SMEM_BYTES = OFF_SLAB + NWARP * SLABF * 4;   // 180608
}

// ---------------- helpers ----------------
__device__ __forceinline__ void split2(float x, float y, uint32_t& h, uint32_t& l) {
    __nv_bfloat162 hb = __floats2bfloat162_rn(x, y);        // x -> low, y -> high
    h = *(const uint32_t*)&hb;
    float rx = x - __bfloat162float(hb.x);
    float ry = y - __bfloat162float(hb.y);
    __nv_bfloat162 lb = __floats2bfloat162_rn(rx, ry);
    l = *(const uint32_t*)&lb;
}
__device__ __forceinline__ void mma16816(float (&d)[4], const uint32_t (&a)[4],
                                         uint32_t b0, uint32_t b1) {
    asm volatile(
        "mma.sync.aligned.m16n8k16.row.col.f32.bf16.bf16.f32 "
        "{%0,%1,%2,%3}, {%4,%5,%6,%7}, {%8,%9}, {%0,%1,%2,%3};"
        : "+f"(d[0]), "+f"(d[1]), "+f"(d[2]), "+f"(d[3])
        : "r"(a[0]), "r"(a[1]), "r"(a[2]), "r"(a[3]), "r"(b0), "r"(b1));
}

// ---------------- device scratch ----------------
__device__ float g_h0[cfg::NN * 16];
__device__ float g_h1[cfg::NN * 12];
__device__ float g_acc0[cfg::NN * 16];
__device__ float g_acc1[cfg::NN * 12];
__device__ float g_cnt[cfg::NN];
__device__ float g_eattr[cfg::NE * 16];
__device__ float g_y1[cfg::NE * 3];
// pre-packed weight fragments, both layers
__device__ uint4 g_B2F[2 * 52 * 4 * 32];   // 212992 B
__device__ uint4 g_B1F[2 * 8 * 3 * 32];    // 24576 B

// ---------------- zero scratch + pack weight fragments (both layers) ----------------
__global__ void zero_pack_kernel(const float* __restrict__ fc1W,
                                 const float* __restrict__ fc2W) {
    int i = blockIdx.x * blockDim.x + threadIdx.x;
    int stride = gridDim.x * blockDim.x;

    if (i < 2 * 6656) {
        int layer = i / 6656, t = i - layer * 6656;
        const float* W2g = fc2W + layer * 64 * 416;
        int nt = t >> 7, rem = t & 127, ks = rem >> 5, ln = rem & 31;
        int gg = ln >> 2, cc = ln & 3;
        int n = nt * 8 + gg, k0 = ks * 16 + 2 * cc;
        uint32_t hx, lx, hy, ly;
        split2(W2g[k0 * 416 + n], W2g[(k0 + 1) * 416 + n], hx, lx);
        split2(W2g[(k0 + 8) * 416 + n], W2g[(k0 + 9) * 416 + n], hy, ly);
        g_B2F[layer * 6656 + t] = make_uint4(hx, hy, lx, ly);
    } else if (i < 2 * 6656 + 2 * 768) {
        int j = i - 2 * 6656;
        int layer = j / 768, t = j - layer * 768;
        const float* W1g = fc1W + layer * 48 * 64;
        int nt = t / 96, rem = t % 96, ks = rem >> 5, ln = rem & 31;
        int gg = ln >> 2, cc = ln & 3;
        int n = nt * 8 + gg, k0 = ks * 16 + 2 * cc;
        uint32_t hx, lx, hy, ly;
        split2(W1g[k0 * 64 + n], W1g[(k0 + 1) * 64 + n], hx, lx);
        split2(W1g[(k0 + 8) * 64 + n], W1g[(k0 + 9) * 64 + n], hy, ly);
        g_B1F[layer * 768 + t] = make_uint4(hx, hy, lx, ly);
    }

    for (int t = i; t < cfg::NN * 16; t += stride) g_acc0[t] = 0.f;
    for (int t = i; t < cfg::NN * 12; t += stride) { g_acc1[t] = 0.f; g_h1[t] = 0.f; }
    for (int t = i; t < cfg::NN; t += stride) g_cnt[t] = 0.f;
}

// ---------------- fused node MLP + edge init (block-range partitioned) ----------------
// Race-free: node region writes only g_h0; edge region reads pos/eain/ei and
// writes g_eattr/g_y1 + atomics into g_cnt (zeroed by zero_pack_kernel earlier).
__global__ void ne_init_kernel(const float* __restrict__ nf,
                               const float* __restrict__ encW, const float* __restrict__ encB,
                               const float* __restrict__ nW1, const float* __restrict__ nB1,
                               const float* __restrict__ nW2, const float* __restrict__ nB2,
                               const float* __restrict__ pos,
                               const float* __restrict__ eain, const int* __restrict__ ei,
                               const float* __restrict__ eeW1, const float* __restrict__ eeB1,
                               const float* __restrict__ eeW2, const float* __restrict__ eeB2,
                               const float* __restrict__ reW1, const float* __restrict__ reB1,
                               const float* __restrict__ reW2, const float* __restrict__ reB2) {
    const int bid = blockIdx.x, tid = threadIdx.x;

    if (bid < cfg::NE_ND_BLKS) {
        // ---- node encoder + node_embedding MLP ----
        int n = bid * 256 + tid;
        if (n >= cfg::NN) return;
        float enc[16];
        #pragma unroll
        for (int c = 0; c < 16; c++) enc[c] = encB[c];
        for (int f = 0; f < 64; f++) {
            float v = nf[n * 64 + f];
            #pragma unroll
            for (int c = 0; c < 16; c++) enc[c] = fmaf(v, encW[f * 16 + c], enc[c]);
        }
        float t[16];
        #pragma unroll
        for (int c = 0; c < 16; c++) {
            float a = nB1[c];
            #pragma unroll
            for (int j = 0; j < 16; j++) a = fmaf(enc[j], nW1[j * 16 + c], a);
            t[c] = fmaxf(a, 0.f);
        }
        #pragma unroll
        for (int c = 0; c < 16; c++) {
            float a = nB2[c];
            #pragma unroll
            for (int j = 0; j < 16; j++) a = fmaf(t[j], nW2[j * 16 + c], a);
            g_h0[n * 16 + c] = a;
        }
        return;
    }

    // ---- per-edge: geometry, rbf (unrolled 32-expf), edge_attr, degree ----
    int e = (bid - cfg::NE_ND_BLKS) * 256 + tid;
    if (e >= cfg::NE) return;
    int sn = ei[e], dn = ei[cfg::NE + e];
    float vx = pos[sn * 3 + 0] - pos[dn * 3 + 0];
    float vy = pos[sn * 3 + 1] - pos[dn * 3 + 1];
    float vz = pos[sn * 3 + 2] - pos[dn * 3 + 2];
    float d = sqrtf(vx * vx + vy * vy + vz * vz);
    float dmx = fmaxf(d, 1e-9f);
    float s = 1.7320508075688772f / dmx;
    g_y1[e * 3 + 0] = s * vx;
    g_y1[e * 3 + 1] = s * vy;
    g_y1[e * 3 + 2] = s * vz;
    atomicAdd(&g_cnt[sn], 1.f);

    float xin[16];
    #pragma unroll
    for (int j = 0; j < 16; j++) xin[j] = eain[e * 16 + j];
    float he[16];
    #pragma unroll
    for (int c = 0; c < 16; c++) {
        float a = eeB1[c];
        #pragma unroll
        for (int j = 0; j < 16; j++) a = fmaf(xin[j], eeW1[j * 16 + c], a);
        he[c] = fmaxf(a, 0.f);
    }
    const float step = 12.0f / 31.0f;
    const float coeff = -0.5f / (step * step);
    float hr[16];
    #pragma unroll
    for (int c = 0; c < 16; c++) hr[c] = reB1[c];
    #pragma unroll 4
    for (int r = 0; r < 32; r++) {
        float t = d - (float)r * step;
        float rb = __expf(coeff * t * t);
        #pragma unroll
        for (int c = 0; c < 16; c++) hr[c] = fmaf(rb, reW1[r * 16 + c], hr[c]);
    }
    #pragma unroll
    for (int c = 0; c < 16; c++) hr[c] = fmaxf(hr[c], 0.f);
    #pragma unroll
    for (int c = 0; c < 16; c++) {
        float a = eeB2[c] + reB2[c];
        #pragma unroll
        for (int j = 0; j < 16; j++)
            a = fmaf(he[j], eeW2[j * 16 + c], fmaf(hr[j], reW2[j * 16 + c], a));
        g_eattr[e * 16 + c] = a;
    }
}

// ---------------- conv layer: mma.sync split-bf16, 2 M-tiles per warp ----------------
__global__ void __launch_bounds__(cfg::THREADS, 1)
conv_kernel(const int* __restrict__ ei, int layer,
            const float* __restrict__ B1g, const float* __restrict__ B2g) {
    extern __shared__ char sm[];
    uint4* B2F = (uint4*)(sm + cfg::OFF_B2F);
    uint4* B1F = (uint4*)(sm + cfg::OFF_B1F);
    float* bias2s = (float*)(sm + cfg::OFF_BIAS2);
    float* bias1s = (float*)(sm + cfg::OFF_BIAS1);
    const int tid = threadIdx.x, lane = tid & 31, warp = tid >> 5;
    const int g = lane >> 2, c = lane & 3;

    // ---- coalesced copy of pre-packed weight fragments ----
    const uint4* src2 = g_B2F + layer * 6656;
    const uint4* src1 = g_B1F + layer * 768;
    for (int t = tid; t < 6656; t += cfg::THREADS) B2F[t] = src2[t];
    for (int t = tid; t < 768; t += cfg::THREADS) B1F[t] = src1[t];
    for (int t = tid; t < 416; t += cfg::THREADS) bias2s[t] = B2g[t];
    for (int t = tid; t < 64; t += cfg::THREADS) bias1s[t] = B1g[t];
    __syncthreads();

    float* sl  = (float*)(sm + cfg::OFF_SLAB) + warp * cfg::SLABF;
    float* X0  = sl;           // [32][20]
    float* X1  = sl + 640;     // [32][12]
    float* DOT = sl + 1024;    // [32][4]
    float* CR  = sl + 1152;    // [32][12]
    float* Y1s = sl + 1536;    // [32][3]

    const unsigned FULL = 0xffffffffu;
    const float n0sc = 0.22360679774997896f;   // 1/sqrt(20)
    const float n1sc = 0.20412414523193150f;   // 1/sqrt(24)

    for (int blk = blockIdx.x * cfg::NWARP + warp; blk < cfg::NBLK;
         blk += gridDim.x * cfg::NWARP) {
        const int ebase = blk * 32;

        // ---- stage per-edge data: each lane owns one of 32 edges ----
        {
            int e = lane, ge = ebase + e;
            int dn = ei[cfg::NE + ge];
            const float4* p = (const float4*)(g_h0 + (size_t)dn * 16);
            *(float4*)(X0 + e * 20 + 0)  = p[0];
            *(float4*)(X0 + e * 20 + 4)  = p[1];
            *(float4*)(X0 + e * 20 + 8)  = p[2];
            *(float4*)(X0 + e * 20 + 12) = p[3];
            float ya = g_y1[ge * 3 + 0], yb = g_y1[ge * 3 + 1], yc = g_y1[ge * 3 + 2];
            Y1s[e * 3 + 0] = ya; Y1s[e * 3 + 1] = yb; Y1s[e * 3 + 2] = yc;
            float x1r[12];
            #pragma unroll
            for (int q = 0; q < 3; q++)
                ((float4*)x1r)[q] = ((const float4*)(g_h1 + (size_t)dn * 12))[q];
            #pragma unroll
            for (int n = 0; n < 4; n++) {
                float xa = x1r[n*3], xb = x1r[n*3+1], xc = x1r[n*3+2];
                X1[e*12 + n*3 + 0] = xa; X1[e*12 + n*3 + 1] = xb; X1[e*12 + n*3 + 2] = xc;
                DOT[e*4 + n] = (xa*ya + xb*yb + xc*yc) * 0.57735026918962576f;
                CR[e*12 + n*3 + 0] = (xb*yc - xc*yb) * 0.70710678118654752f;
                CR[e*12 + n*3 + 1] = (xc*ya - xa*yc) * 0.70710678118654752f;
                CR[e*12 + n*3 + 2] = (xa*yb - xb*ya) * 0.70710678118654752f;
            }
        }
        __syncwarp();

        // ---- fc1 per tile -> fc2 A-fragments (register chain) ----
        uint32_t a2h[2][4][4], a2l[2][4][4];
        #pragma unroll
        for (int t = 0; t < 2; t++) {
            const int gx0 = ebase + t * 16 + g, gx1 = gx0 + 8;
            const int sn0 = ei[gx0], sn1 = ei[gx1];
            const int dn0 = ei[cfg::NE + gx0], dn1 = ei[cfg::NE + gx1];
            const float* seg0[3] = { g_eattr + (size_t)gx0 * 16, g_h0 + (size_t)sn0 * 16, g_h0 + (size_t)dn0 * 16 };
            const float* seg1[3] = { g_eattr + (size_t)gx1 * 16, g_h0 + (size_t)sn1 * 16, g_h0 + (size_t)dn1 * 16 };

            uint32_t a1h[3][4], a1l[3][4];
            #pragma unroll
            for (int ks = 0; ks < 3; ks++) {
                float2 r0lo = *(const float2*)(seg0[ks] + 2 * c);
                float2 r0hi = *(const float2*)(seg0[ks] + 2 * c + 8);
                float2 r1lo = *(const float2*)(seg1[ks] + 2 * c);
                float2 r1hi = *(const float2*)(seg1[ks] + 2 * c + 8);
                split2(r0lo.x, r0lo.y, a1h[ks][0], a1l[ks][0]);
                split2(r1lo.x, r1lo.y, a1h[ks][1], a1l[ks][1]);
                split2(r0hi.x, r0hi.y, a1h[ks][2], a1l[ks][2]);
                split2(r1hi.x, r1hi.y, a1h[ks][3], a1l[ks][3]);
            }
            float d1[8][4];
            #pragma unroll
            for (int nt = 0; nt < 8; nt++) { d1[nt][0]=0.f; d1[nt][1]=0.f; d1[nt][2]=0.f; d1[nt][3]=0.f; }
            #pragma unroll
            for (int nt = 0; nt < 8; nt++)
                #pragma unroll
                for (int ks = 0; ks < 3; ks++) {
                    uint4 B = B1F[(nt * 3 + ks) * 32 + lane];
                    mma16816(d1[nt], a1h[ks], B.x, B.y);
                    mma16816(d1[nt], a1h[ks], B.z, B.w);
                    mma16816(d1[nt], a1l[ks], B.x, B.y);
                }
            #pragma unroll
            for (int nt = 0; nt < 8; nt++) {
                float b0 = bias1s[nt * 8 + 2 * c], b1 = bias1s[nt * 8 + 2 * c + 1];
                float v0 = fmaxf(d1[nt][0] + b0, 0.f), v1 = fmaxf(d1[nt][1] + b1, 0.f);
                float v2 = fmaxf(d1[nt][2] + b0, 0.f), v3 = fmaxf(d1[nt][3] + b1, 0.f);
                int ks2 = nt >> 1, sl2 = (nt & 1) * 2;
                split2(v0, v1, a2h[t][ks2][sl2],     a2l[t][ks2][sl2]);
                split2(v2, v3, a2h[t][ks2][sl2 + 1], a2l[t][ks2][sl2 + 1]);
            }
        }

        // ---- fc2 + tensor-product contraction, per column-pair, both tiles ----
        float o0a[2][2][4];
        #pragma unroll
        for (int t = 0; t < 2; t++)
            #pragma unroll
            for (int r = 0; r < 2; r++) { o0a[t][r][0]=0.f; o0a[t][r][1]=0.f; o0a[t][r][2]=0.f; o0a[t][r][3]=0.f; }
        float t011p[2][2][2] = {{{0.f,0.f},{0.f,0.f}},{{0.f,0.f},{0.f,0.f}}};
        float o1p[2][2][2][3];
        #pragma unroll
        for (int t = 0; t < 2; t++)
            #pragma unroll
            for (int r = 0; r < 2; r++)
                #pragma unroll
                for (int s = 0; s < 2; s++) { o1p[t][r][s][0]=0.f; o1p[t][r][s][1]=0.f; o1p[t][r][s][2]=0.f; }

        #define FC2_PAIR(j, dA, dB)                                             \
            float dA[2][4] = {{0.f,0.f,0.f,0.f},{0.f,0.f,0.f,0.f}};             \
            float dB[2][4] = {{0.f,0.f,0.f,0.f},{0.f,0.f,0.f,0.f}};             \
            {   int ntA = 2 * (j);                                              \
                _Pragma("unroll")                                               \
                for (int ks = 0; ks < 4; ks++) {                                \
                    uint4 BA = B2F[(ntA * 4 + ks) * 32 + lane];                 \
                    uint4 BB = B2F[((ntA + 1) * 4 + ks) * 32 + lane];           \
                    _Pragma("unroll")                                           \
                    for (int t = 0; t < 2; t++) {                               \
                        mma16816(dA[t], a2h[t][ks], BA.x, BA.y);                \
                        mma16816(dA[t], a2h[t][ks], BA.z, BA.w);                \
                        mma16816(dA[t], a2l[t][ks], BA.x, BA.y);                \
                        mma16816(dB[t], a2h[t][ks], BB.x, BB.y);                \
                        mma16816(dB[t], a2h[t][ks], BB.z, BB.w);                \
                        mma16816(dB[t], a2l[t][ks], BB.x, BB.y);                \
                    }                                                           \
                } }                                                             \
            {   float bA0 = bias2s[16*(j) + 2*c],     bA1 = bias2s[16*(j) + 2*c + 1]; \
                float bB0 = bias2s[16*(j) + 8 + 2*c], bB1 = bias2s[16*(j) + 9 + 2*c]; \
                _Pragma("unroll")                                               \
                for (int t = 0; t < 2; t++) {                                   \
                    dA[t][0] += bA0; dA[t][1] += bA1; dA[t][2] += bA0; dA[t][3] += bA1; \
                    dB[t][0] += bB0; dB[t][1] += bB1; dB[t][2] += bB0; dB[t][3] += bB1; \
                } }

        // pairs 0..15: w00  (o0 += x0[n=j] * w)
        for (int j = 0; j < 16; j++) {
            FC2_PAIR(j, dA, dB);
            #pragma unroll
            for (int t = 0; t < 2; t++) {
                int e0 = t * 16 + g, e1 = e0 + 8;
                float xa = X0[e0 * 20 + j], xb = X0[e1 * 20 + j];
                o0a[t][0][0] = fmaf(xa, dA[t][0], o0a[t][0][0]); o0a[t][0][1] = fmaf(xa, dA[t][1], o0a[t][0][1]);
                o0a[t][0][2] = fmaf(xa, dB[t][0], o0a[t][0][2]); o0a[t][0][3] = fmaf(xa, dB[t][1], o0a[t][0][3]);
                o0a[t][1][0] = fmaf(xb, dA[t][2], o0a[t][1][0]); o0a[t][1][1] = fmaf(xb, dA[t][3], o0a[t][1][1]);
                o0a[t][1][2] = fmaf(xb, dB[t][2], o0a[t][1][2]); o0a[t][1][3] = fmaf(xb, dB[t][3], o0a[t][1][3]);
            }
        }
        // pairs 16..19: w011 (t011[o] += x0[n] * w)
        for (int j = 16; j < 20; j++) {
            FC2_PAIR(j, dA, dB);
            int nA = 4 * (j - 16) + (c >> 1), nB = nA + 2;
            #pragma unroll
            for (int t = 0; t < 2; t++) {
                int e0 = t * 16 + g, e1 = e0 + 8;
                float xa0 = X0[e0*20 + nA], xb0 = X0[e0*20 + nB];
                float xa1 = X0[e1*20 + nA], xb1 = X0[e1*20 + nB];
                t011p[t][0][0] += xa0 * dA[t][0] + xb0 * dB[t][0];
                t011p[t][0][1] += xa0 * dA[t][1] + xb0 * dB[t][1];
                t011p[t][1][0] += xa1 * dA[t][2] + xb1 * dB[t][2];
                t011p[t][1][1] += xa1 * dA[t][3] + xb1 * dB[t][3];
            }
        }
        // pair 20: w101 (o1[o][m] += x1[n][m] * w)
        {
            FC2_PAIR(20, dA, dB);
            int nA = c >> 1, nB = nA + 2;
            #pragma unroll
            for (int t = 0; t < 2; t++) {
                int e0 = t * 16 + g, e1 = e0 + 8;
                #pragma unroll
                for (int m = 0; m < 3; m++) {
                    float xa0 = X1[e0*12 + nA*3 + m], xb0 = X1[e0*12 + nB*3 + m];
                    float xa1 = X1[e1*12 + nA*3 + m], xb1 = X1[e1*12 + nB*3 + m];
                    o1p[t][0][0][m] += xa0 * dA[t][0] + xb0 * dB[t][0];
                    o1p[t][0][1][m] += xa0 * dA[t][1] + xb0 * dB[t][1];
                    o1p[t][1][0][m] += xa1 * dA[t][2] + xb1 * dB[t][2];
                    o1p[t][1][1][m] += xa1 * dA[t][3] + xb1 * dB[t][3];
                }
            }
        }
        // pairs 21..24: w110 (o0 += dot[n=j-21] * w)
        for (int j = 21; j < 25; j++) {
            FC2_PAIR(j, dA, dB);
            #pragma unroll
            for (int t = 0; t < 2; t++) {
                int e0 = t * 16 + g, e1 = e0 + 8;
                float da = DOT[e0*4 + (j - 21)], db = DOT[e1*4 + (j - 21)];
                o0a[t][0][0] = fmaf(da, dA[t][0], o0a[t][0][0]); o0a[t][0][1] = fmaf(da, dA[t][1], o0a[t][0][1]);
                o0a[t][0][2] = fmaf(da, dB[t][0], o0a[t][0][2]); o0a[t][0][3] = fmaf(da, dB[t][1], o0a[t][0][3]);
                o0a[t][1][0] = fmaf(db, dA[t][2], o0a[t][1][0]); o0a[t][1][1] = fmaf(db, dA[t][3], o0a[t][1][1]);
                o0a[t][1][2] = fmaf(db, dB[t][2], o0a[t][1][2]); o0a[t][1][3] = fmaf(db, dB[t][3], o0a[t][1][3]);
            }
        }
        // pair 25: w111 (o1 += cr[n][m] * w)
        {
            FC2_PAIR(25, dA, dB);
            int nA = c >> 1, nB = nA + 2;
            #pragma unroll
            for (int t = 0; t < 2; t++) {
                int e0 = t * 16 + g, e1 = e0 + 8;
                #pragma unroll
                for (int m = 0; m < 3; m++) {
                    float xa0 = CR[e0*12 + nA*3 + m], xb0 = CR[e0*12 + nB*3 + m];
                    float xa1 = CR[e1*12 + nA*3 + m], xb1 = CR[e1*12 + nB*3 + m];
                    o1p[t][0][0][m] += xa0 * dA[t][0] + xb0 * dB[t][0];
                    o1p[t][0][1][m] += xa0 * dA[t][1] + xb0 * dB[t][1];
                    o1p[t][1][0][m] += xa1 * dA[t][2] + xb1 * dB[t][2];
                    o1p[t][1][1][m] += xa1 * dA[t][3] + xb1 * dB[t][3];
                }
            }
        }
        #undef FC2_PAIR

        // ---- l=0 scatter ----
        #pragma unroll
        for (int t = 0; t < 2; t++)
            #pragma unroll
            for (int r = 0; r < 2; r++) {
                int sn = ei[ebase + t * 16 + g + r * 8];
                #pragma unroll
                for (int s = 0; s < 4; s++) {
                    int o = (s < 2) ? (2 * c + s) : (8 + 2 * c + (s - 2));
                    atomicAdd(&g_acc0[sn * 16 + o], n0sc * o0a[t][r][s]);
                }
            }
        // ---- l=1: reduce across c<->c^2, add t011*y1, scatter ----
        #pragma unroll
        for (int t = 0; t < 2; t++)
            #pragma unroll
            for (int r = 0; r < 2; r++)
                #pragma unroll
                for (int s = 0; s < 2; s++) {
                    t011p[t][r][s] += __shfl_xor_sync(FULL, t011p[t][r][s], 2);
                    #pragma unroll
                    for (int m = 0; m < 3; m++)
                        o1p[t][r][s][m] += __shfl_xor_sync(FULL, o1p[t][r][s][m], 2);
                }
        if (c < 2) {
            #pragma unroll
            for (int t = 0; t < 2; t++)
                #pragma unroll
                for (int r = 0; r < 2; r++) {
                    int e = t * 16 + g + r * 8;
                    int sn = ei[ebase + e];
                    #pragma unroll
                    for (int s = 0; s < 2; s++) {
                        int o = 2 * c + s;
                        float tt = t011p[t][r][s];
                        #pragma unroll
                        for (int m = 0; m < 3; m++) {
                            float val = o1p[t][r][s][m] + tt * Y1s[e * 3 + m];
                            atomicAdd(&g_acc1[sn * 12 + o * 3 + m], n1sc * val);
                        }
                    }
                }
        }
        __syncwarp();
    }
}

// ---------------- scatter-mean residual update ----------------
__global__ void update_kernel() {
    int i = blockIdx.x * blockDim.x + threadIdx.x;
    if (i < cfg::NN * 16) {
        int n = i >> 4;
        float inv = 1.f / fmaxf(g_cnt[n], 1.f);
        g_h0[i] += g_acc0[i] * inv;
        g_acc0[i] = 0.f;
    }
    if (i < cfg::NN * 12) {
        int n = i / 12;
        float inv = 1.f / fmaxf(g_cnt[n], 1.f);
        g_h1[i] += g_acc1[i] * inv;
        g_acc1[i] = 0.f;
    }
}

// ---------------- final update + o3.Linear + sorter ----------------
__global__ void final_kernel(float* __restrict__ out,
                             const float* __restrict__ lin0, const float* __restrict__ lin1) {
    int n = blockIdx.x * blockDim.x + threadIdx.x;
    if (n >= cfg::NN) return;
    float inv = 1.f / fmaxf(g_cnt[n], 1.f);
    float h0f[16];
    #pragma unroll
    for (int s = 0; s < 16; s++) h0f[s] = g_h0[n * 16 + s] + g_acc0[n * 16 + s] * inv;
    float h1f[12];
    #pragma unroll
    for (int s = 0; s < 12; s++) h1f[s] = g_h1[n * 12 + s] + g_acc1[n * 12 + s] * inv;
    float* o = out + (size_t)n * 128;
    #pragma unroll 4
    for (int cc = 0; cc < 32; cc++) {
        float f0 = 0.f;
        #pragma unroll
        for (int s = 0; s < 16; s++) f0 = fmaf(h0f[s], lin0[s * 32 + cc], f0);
        o[4 * cc] = 0.25f * f0;
        #pragma unroll
        for (int m = 0; m < 3; m++) {
            float f1 = 0.f;
            #pragma unroll
            for (int v = 0; v < 4; v++) f1 = fmaf(h1f[v * 3 + m], lin1[v * 32 + cc], f1);
            o[4 * cc + 1 + m] = 0.5f * f1;
        }
    }
}

// ---------------- launch ----------------
extern "C" void kernel_launch(void* const* d_in, const int* in_sizes, int n_in,
                              void* d_out, int out_size) {
    const float* pos          = (const float*)d_in[0];
    const float* node_feats   = (const float*)d_in[1];
    const float* edge_attr_in = (const float*)d_in[2];
    const int*   edge_index   = (const int*)d_in[3];
    const float* enc_W  = (const float*)d_in[4];
    const float* enc_b  = (const float*)d_in[5];
    const float* ne_W1  = (const float*)d_in[6];
    const float* ne_b1  = (const float*)d_in[7];
    const float* ne_W2  = (const float*)d_in[8];
    const float* ne_b2  = (const float*)d_in[9];
    const float* ee_W1  = (const float*)d_in[10];
    const float* ee_b1  = (const float*)d_in[11];
    const float* ee_W2  = (const float*)d_in[12];
    const float* ee_b2  = (const float*)d_in[13];
    const float* re_W1  = (const float*)d_in[14];
    const float* re_b1  = (const float*)d_in[15];
    const float* re_W2  = (const float*)d_in[16];
    const float* re_b2  = (const float*)d_in[17];
    const float* fc1_W  = (const float*)d_in[18];   // [2,48,64]
    const float* fc1_b  = (const float*)d_in[19];   // [2,64]
    const float* fc2_W  = (const float*)d_in[20];   // [2,64,416]
    const float* fc2_b  = (const float*)d_in[21];   // [2,416]
    const float* lin0_W = (const float*)d_in[22];
    const float* lin1_W = (const float*)d_in[23];
    float* out = (float*)d_out;

    int dev = 0;
    cudaGetDevice(&dev);
    int nsm = 148;
    cudaDeviceGetAttribute(&nsm, cudaDevAttrMultiProcessorCount, dev);
    cudaFuncSetAttribute(conv_kernel, cudaFuncAttributeMaxDynamicSharedMemorySize, cfg::SMEM_BYTES);

    zero_pack_kernel<<<256, 256>>>(fc1_W, fc2_W);
    ne_init_kernel<<<cfg::NE_BLKS, 256>>>(node_feats, enc_W, enc_b,
                                          ne_W1, ne_b1, ne_W2, ne_b2,
                                          pos, edge_attr_in, edge_index,
                                          ee_W1, ee_b1, ee_W2, ee_b2,
                                          re_W1, re_b1, re_W2, re_b2);
    // layer 0
    conv_kernel<<<nsm, cfg::THREADS, cfg::SMEM_BYTES>>>(edge_index, 0, fc1_b, fc2_b);
    update_kernel<<<(cfg::NN * 16 + 255) / 256, 256>>>();
    // layer 1
    conv_kernel<<<nsm, cfg::THREADS, cfg::SMEM_BYTES>>>(edge_index, 1,
        fc1_b + 64, fc2_b + 416);
    // final
    final_kernel<<<(cfg::NN + 127) / 128, 128>>>(out, lin0_W, lin1_W);
}